// round 15
// baseline (speedup 1.0000x reference)
#include <cuda_runtime.h>
#include <cuda_bf16.h>
#include <cuda_fp16.h>
#include <math.h>
#include <cstdint>

#define PB 8
#define NNODES_PER_B 2048
#define DD 128
#define HH 256
#define NODES (PB * NNODES_PER_B)   // 16384
#define TABP 4096
#define TABR 16.0f

// ---------------- device scratch ----------------
__device__ __align__(16) __half2 g_tableP[TABP * DD]; // 2 MB paired fp16 (f_i, f_{i+1})
__device__ __align__(16) __half2 g_hh[NODES * 64];    // 4 MB fp16 copy of h (edge gather only)
__device__ float g_sums[NODES * DD];                  // 8 MB scatter-sum
__device__ float g_cnt[NODES];
__device__ int   g_oddOr;
__device__ __align__(16) __nv_bfloat16 g_w3h[256 * 256];
__device__ __align__(16) __nv_bfloat16 g_w3l[256 * 256];
__device__ __align__(16) __nv_bfloat16 g_w4h[128 * 256];
__device__ __align__(16) __nv_bfloat16 g_w4l[128 * 256];

// ---------------- kernel 1: zero scratch + detect edge dtype + h->fp16 ----------------
__global__ void zero_kernel(const int* __restrict__ ei, const float* __restrict__ h) {
    int idx = blockIdx.x * blockDim.x + threadIdx.x;
    int stride = gridDim.x * blockDim.x;
    float4 z = make_float4(0.f, 0.f, 0.f, 0.f);
    const int n4 = (NODES * DD) / 4;
    for (int i = idx; i < n4; i += stride) ((float4*)g_sums)[i] = z;
    const int c4 = NODES / 4;
    for (int i = idx; i < c4; i += stride) ((float4*)g_cnt)[i] = z;
    const int nh2 = NODES * 64;
    for (int i = idx; i < nh2; i += stride) {
        float2 v = ((const float2*)h)[i];
        g_hh[i] = __floats2half2_rn(v.x, v.y);
    }
    if (blockIdx.x == 0) {
        if (threadIdx.x == 0) g_oddOr = 0;
        __syncthreads();
        int acc = 0;
        for (int k = threadIdx.x; k < 2048; k += blockDim.x) acc |= ei[2 * k + 1];
        if (acc) atomicOr(&g_oddOr, acc);
    }
}

// ---------------- kernel 3: build filter table, write fp16 pairs directly ----------------
__global__ void table_kernel(const float* __restrict__ W1, const float* __restrict__ b1,
                             const float* __restrict__ W2, const float* __restrict__ b2) {
    __shared__ float s[36 * 256];
    const int tid = threadIdx.x;
    const int pBase = blockIdx.x * 32;
    const float delta = TABR / (float)(TABP - 1);

    for (int idx = tid; idx < 33 * 256; idx += 128) {
        int j = idx / 33, p = idx - j * 33;
        int pt = pBase + p;
        if (pt > TABP - 1) pt = TABP - 1;
        float t = (float)pt * delta;
        float a = t * W1[j] + b1[j];
        s[j * 36 + p] = a / (1.0f + __expf(-a));
    }
    __syncthreads();

    const int d = tid;   // 0..127
    float acc[33];
#pragma unroll
    for (int p = 0; p < 33; p++) acc[p] = 0.f;

    for (int j = 0; j < 256; j++) {
        float w = W2[j * DD + d];
        const float4* sp = (const float4*)(s + j * 36);
#pragma unroll
        for (int q = 0; q < 8; q++) {
            float4 sv = sp[q];
            acc[4 * q + 0] += sv.x * w; acc[4 * q + 1] += sv.y * w;
            acc[4 * q + 2] += sv.z * w; acc[4 * q + 3] += sv.w * w;
        }
        acc[32] += s[j * 36 + 32] * w;
    }
    float bb = b2[d];
#pragma unroll
    for (int p = 0; p < 32; p++)
        g_tableP[(size_t)(pBase + p) * DD + d] = __floats2half2_rn(acc[p] + bb, acc[p + 1] + bb);
}

// ---------------- kernel 3b: split weights (transposed [N][K], bf16 hi/lo) ----------------
__global__ void wsplit_kernel(const float* __restrict__ W3, const float* __restrict__ W4) {
    int idx = blockIdx.x * blockDim.x + threadIdx.x;
    if (idx < 256 * 256) {
        int n = idx >> 8, k = idx & 255;
        float v = W3[k * 256 + n];
        __nv_bfloat16 hi = __float2bfloat16_rn(v);
        g_w3h[idx] = hi;
        g_w3l[idx] = __float2bfloat16_rn(v - __bfloat162float(hi));
    } else if (idx < 256 * 256 + 128 * 256) {
        int j = idx - 256 * 256;
        int n = j >> 8, k = j & 255;
        float v = W4[k * 128 + n];
        __nv_bfloat16 hi = __float2bfloat16_rn(v);
        g_w4h[j] = hi;
        g_w4l[j] = __float2bfloat16_rn(v - __bfloat162float(hi));
    }
}

// ---------------- kernel 4: edge kernel, 4 edges per warp ----------------
// Quarter-warp (8 lanes) per edge; lane covers dims {4l..}, {32+4l..}, {64+4l..}, {96+4l..}.
__global__ void edge_kernel(const float* __restrict__ x, const void* __restrict__ eiv, int E) {
    int gt = blockIdx.x * blockDim.x + threadIdx.x;
    int e = (gt >> 5) * 4 + ((threadIdx.x >> 3) & 3);
    int l = threadIdx.x & 7;           // lane within quarter-warp
    if (e >= E) return;

    int row, col;
    if (g_oddOr == 0) {
        const long long* p = (const long long*)eiv;
        row = (int)p[e]; col = (int)p[E + e];
    } else {
        const int* p = (const int*)eiv;
        row = p[e]; col = p[E + e];
    }
    float dx = x[row * 3 + 0] - x[col * 3 + 0];
    float dy = x[row * 3 + 1] - x[col * 3 + 1];
    float dz = x[row * 3 + 2] - x[col * 3 + 2];
    float dist = sqrtf(dx * dx + dy * dy + dz * dz);
    float t = dist * ((float)(TABP - 1) / TABR);
    int i0 = (int)t;
    if (i0 > TABP - 2) i0 = TABP - 2;
    float fr = t - (float)i0;

    const uint4* tp = (const uint4*)(g_tableP + (size_t)i0 * DD);
    const uint2* hp = (const uint2*)(g_hh + (size_t)col * 64);
    float* dst = g_sums + (size_t)row * DD;

#pragma unroll
    for (int q = 0; q < 4; q++) {
        uint4 pv = tp[l + q * 8];
        uint2 hv = hp[l + q * 8];
        float2 a0 = __half22float2(*(const __half2*)&pv.x);
        float2 a1 = __half22float2(*(const __half2*)&pv.y);
        float2 a2 = __half22float2(*(const __half2*)&pv.z);
        float2 a3 = __half22float2(*(const __half2*)&pv.w);
        float2 h01 = __half22float2(*(const __half2*)&hv.x);
        float2 h23 = __half22float2(*(const __half2*)&hv.y);
        float m0 = h01.x * (a0.x + fr * (a0.y - a0.x));
        float m1 = h01.y * (a1.x + fr * (a1.y - a1.x));
        float m2 = h23.x * (a2.x + fr * (a2.y - a2.x));
        float m3 = h23.y * (a3.x + fr * (a3.y - a3.x));
        asm volatile("red.global.add.v4.f32 [%0], {%1, %2, %3, %4};"
                     :: "l"(dst + q * 32 + l * 4), "f"(m0), "f"(m1), "f"(m2), "f"(m3) : "memory");
    }
    if (l == 0)
        asm volatile("red.global.add.f32 [%0], %1;" :: "l"(&g_cnt[row]), "f"(1.0f) : "memory");
}

// ---------------- node MLP machinery (R4 verbatim — CONVERGED, do not touch) ----------------
#define PADW 132                        // u32 words per padded row (264 bf16, 528B)
#define OFF_ALO (128 * PADW)
#define OFF_B   (2 * 128 * PADW)
#define SM_U32  (3 * 128 * PADW)        // 202752 B
#define SMEM_NODE (202752 + 1024 * 3 + 512 + 1024 * 2)

__device__ __forceinline__ void mma_bf16(float* c, const uint32_t* a, uint32_t b0, uint32_t b1) {
    asm volatile("mma.sync.aligned.m16n8k16.row.col.f32.bf16.bf16.f32 "
                 "{%0,%1,%2,%3}, {%4,%5,%6,%7}, {%8,%9}, {%0,%1,%2,%3};"
                 : "+f"(c[0]), "+f"(c[1]), "+f"(c[2]), "+f"(c[3])
                 : "r"(a[0]), "r"(a[1]), "r"(a[2]), "r"(a[3]), "r"(b0), "r"(b1));
}
__device__ __forceinline__ uint32_t pack_split(float v0, float v1, uint32_t& lo) {
    __nv_bfloat16 h0 = __float2bfloat16_rn(v0);
    __nv_bfloat16 h1 = __float2bfloat16_rn(v1);
    __nv_bfloat16 l0 = __float2bfloat16_rn(v0 - __bfloat162float(h0));
    __nv_bfloat16 l1 = __float2bfloat16_rn(v1 - __bfloat162float(h1));
    lo = ((uint32_t)__bfloat16_as_ushort(l1) << 16) | __bfloat16_as_ushort(l0);
    return ((uint32_t)__bfloat16_as_ushort(h1) << 16) | __bfloat16_as_ushort(h0);
}

template <int NTBASE>
__device__ __forceinline__ void gemm_pass(const uint32_t* __restrict__ Asm,
                                          const uint32_t* __restrict__ Bsm,
                                          float (&acc)[2][16][4],
                                          int mr, int nwBase, int g, int tg) {
    for (int ks = 0; ks < 16; ks++) {
        uint32_t a[2][4];
#pragma unroll
        for (int mt = 0; mt < 2; mt++) {
            int w = (mr + mt * 16 + g) * PADW + ks * 8 + tg;
            a[mt][0] = Asm[w];
            a[mt][1] = Asm[w + 8 * PADW];
            a[mt][2] = Asm[w + 4];
            a[mt][3] = Asm[w + 8 * PADW + 4];
        }
#pragma unroll
        for (int nt = 0; nt < 8; nt++) {
            int bw = (nwBase + nt * 8 + g) * PADW + ks * 8 + tg;
            uint32_t b0 = Bsm[bw], b1 = Bsm[bw + 4];
            mma_bf16(acc[0][NTBASE + nt], a[0], b0, b1);
            mma_bf16(acc[1][NTBASE + nt], a[1], b0, b1);
        }
    }
}

__device__ __forceinline__ void load_b128(uint4* __restrict__ dstB,
                                          const uint4* __restrict__ src, int nOff) {
    for (int i = threadIdx.x; i < 128 * 32; i += 256) {
        int nl = i >> 5, k4 = i & 31;
        dstB[nl * 33 + k4] = src[(nOff + nl) * 32 + k4];
    }
}

__global__ void __launch_bounds__(256, 1)
node_kernel(const float* __restrict__ h,
            const float* __restrict__ b3, const float* __restrict__ gamma,
            const float* __restrict__ beta, const float* __restrict__ b4,
            float* __restrict__ out) {
    extern __shared__ uint32_t sm[];
    uint32_t* Ahi = sm;
    uint32_t* Alo = sm + OFF_ALO;
    uint32_t* Bsm = sm + OFF_B;
    float* sm_b3 = (float*)(sm + SM_U32);
    float* sm_ga = sm_b3 + 256;
    float* sm_be = sm_ga + 256;
    float* sm_b4 = sm_be + 256;
    float* sm_s1 = sm_b4 + 128;
    float* sm_s2 = sm_s1 + 256;

    const int tid = threadIdx.x;
    const int lane = tid & 31;
    const int wid = tid >> 5;
    const int g = lane >> 2, tg = lane & 3;
    const int mw = wid & 3, nw = wid >> 2;
    const int mr = mw * 32, nwBase = nw * 64;
    const int rowBase = blockIdx.x * 128;

    sm_b3[tid] = b3[tid];
    sm_ga[tid] = gamma[tid];
    sm_be[tid] = beta[tid];
    if (tid < 128) sm_b4[tid] = b4[tid];

    // ---- build A = [h | agg], split hi/lo ----
    for (int idx = tid; idx < 128 * 64; idx += 256) {
        int row = idx >> 6, kp = idx & 63;
        float2 v = ((const float2*)(h + (size_t)(rowBase + row) * DD))[kp];
        uint32_t lo, hi = pack_split(v.x, v.y, lo);
        Ahi[row * PADW + kp] = hi;
        Alo[row * PADW + kp] = lo;
    }
    for (int idx = tid; idx < 128 * 64; idx += 256) {
        int row = idx >> 6, kp = idx & 63;
        int node = rowBase + row;
        float inv = 1.0f / fmaxf(g_cnt[node], 1.0f);
        float2 v = ((const float2*)(g_sums + (size_t)node * DD))[kp];
        uint32_t lo, hi = pack_split(v.x * inv, v.y * inv, lo);
        Ahi[row * PADW + 64 + kp] = hi;
        Alo[row * PADW + 64 + kp] = lo;
    }

    float acc[2][16][4];
#pragma unroll
    for (int mt = 0; mt < 2; mt++)
#pragma unroll
        for (int nt = 0; nt < 16; nt++)
#pragma unroll
            for (int f = 0; f < 4; f++) acc[mt][nt][f] = 0.f;

    // ---- GEMM1: 2 col-chunks; hi*hi + lo*hi + hi*lo ----
#pragma unroll
    for (int chunk = 0; chunk < 2; chunk++) {
        __syncthreads();
        load_b128((uint4*)Bsm, (const uint4*)g_w3h, chunk * 128);
        __syncthreads();
        if (chunk == 0) {
            gemm_pass<0>(Ahi, Bsm, acc, mr, nwBase, g, tg);
            gemm_pass<0>(Alo, Bsm, acc, mr, nwBase, g, tg);
        } else {
            gemm_pass<8>(Ahi, Bsm, acc, mr, nwBase, g, tg);
            gemm_pass<8>(Alo, Bsm, acc, mr, nwBase, g, tg);
        }
        __syncthreads();
        load_b128((uint4*)Bsm, (const uint4*)g_w3l, chunk * 128);
        __syncthreads();
        if (chunk == 0) gemm_pass<0>(Ahi, Bsm, acc, mr, nwBase, g, tg);
        else            gemm_pass<8>(Ahi, Bsm, acc, mr, nwBase, g, tg);
    }
    __syncthreads();

    // ---- epilogue 1: +b3, LayerNorm, SiLU, re-split into A buffers ----
    float s1[4] = {0.f, 0.f, 0.f, 0.f}, s2[4] = {0.f, 0.f, 0.f, 0.f};
#pragma unroll
    for (int mt = 0; mt < 2; mt++)
#pragma unroll
        for (int q = 0; q < 16; q++) {
            int chunk = q >> 3, nt = q & 7;
            int c0 = chunk * 128 + nwBase + nt * 8 + 2 * tg;
            float u0 = acc[mt][q][0] + sm_b3[c0];
            float u1 = acc[mt][q][1] + sm_b3[c0 + 1];
            float u2 = acc[mt][q][2] + sm_b3[c0];
            float u3 = acc[mt][q][3] + sm_b3[c0 + 1];
            acc[mt][q][0] = u0; acc[mt][q][1] = u1;
            acc[mt][q][2] = u2; acc[mt][q][3] = u3;
            s1[mt * 2 + 0] += u0 + u1;  s2[mt * 2 + 0] += u0 * u0 + u1 * u1;
            s1[mt * 2 + 1] += u2 + u3;  s2[mt * 2 + 1] += u2 * u2 + u3 * u3;
        }
#pragma unroll
    for (int r = 0; r < 4; r++) {
#pragma unroll
        for (int off = 1; off < 4; off <<= 1) {
            s1[r] += __shfl_xor_sync(0xffffffffu, s1[r], off);
            s2[r] += __shfl_xor_sync(0xffffffffu, s2[r], off);
        }
    }
    if (tg == 0) {
        int rows[4] = {mr + g, mr + g + 8, mr + 16 + g, mr + 24 + g};
#pragma unroll
        for (int r = 0; r < 4; r++) {
            sm_s1[rows[r] * 2 + nw] = s1[r];
            sm_s2[rows[r] * 2 + nw] = s2[r];
        }
    }
    __syncthreads();
    float mu[4], rs[4];
    {
        int rows[4] = {mr + g, mr + g + 8, mr + 16 + g, mr + 24 + g};
#pragma unroll
        for (int r = 0; r < 4; r++) {
            float S1 = sm_s1[rows[r] * 2] + sm_s1[rows[r] * 2 + 1];
            float S2 = sm_s2[rows[r] * 2] + sm_s2[rows[r] * 2 + 1];
            float m = S1 * (1.0f / 256.0f);
            float var = S2 * (1.0f / 256.0f) - m * m;
            mu[r] = m;
            rs[r] = rsqrtf(var + 1e-5f);
        }
    }
    __syncthreads();
#pragma unroll
    for (int mt = 0; mt < 2; mt++)
#pragma unroll
        for (int q = 0; q < 16; q++) {
            int chunk = q >> 3, nt = q & 7;
            int c0 = chunk * 128 + nwBase + nt * 8 + 2 * tg;
            float ga0 = sm_ga[c0], ga1 = sm_ga[c0 + 1];
            float be0 = sm_be[c0], be1 = sm_be[c0 + 1];
            int rlo = mr + mt * 16 + g;
            {
                float v0 = (acc[mt][q][0] - mu[mt * 2]) * rs[mt * 2] * ga0 + be0;
                float v1 = (acc[mt][q][1] - mu[mt * 2]) * rs[mt * 2] * ga1 + be1;
                float w0 = v0 / (1.0f + __expf(-v0));
                float w1 = v1 / (1.0f + __expf(-v1));
                uint32_t lo, hi = pack_split(w0, w1, lo);
                int word = rlo * PADW + (c0 >> 1);
                Ahi[word] = hi; Alo[word] = lo;
            }
            {
                float v0 = (acc[mt][q][2] - mu[mt * 2 + 1]) * rs[mt * 2 + 1] * ga0 + be0;
                float v1 = (acc[mt][q][3] - mu[mt * 2 + 1]) * rs[mt * 2 + 1] * ga1 + be1;
                float w0 = v0 / (1.0f + __expf(-v0));
                float w1 = v1 / (1.0f + __expf(-v1));
                uint32_t lo, hi = pack_split(w0, w1, lo);
                int word = (rlo + 8) * PADW + (c0 >> 1);
                Ahi[word] = hi; Alo[word] = lo;
            }
        }

    // ---- GEMM2: C2(128x128) = A2 @ W4T^T ----
#pragma unroll
    for (int mt = 0; mt < 2; mt++)
#pragma unroll
        for (int nt = 0; nt < 8; nt++)
#pragma unroll
            for (int f = 0; f < 4; f++) acc[mt][nt][f] = 0.f;

    __syncthreads();
    load_b128((uint4*)Bsm, (const uint4*)g_w4h, 0);
    __syncthreads();
    gemm_pass<0>(Ahi, Bsm, acc, mr, nwBase, g, tg);
    gemm_pass<0>(Alo, Bsm, acc, mr, nwBase, g, tg);
    __syncthreads();
    load_b128((uint4*)Bsm, (const uint4*)g_w4l, 0);
    __syncthreads();
    gemm_pass<0>(Ahi, Bsm, acc, mr, nwBase, g, tg);

    // ---- epilogue 2: +b4, store ----
#pragma unroll
    for (int mt = 0; mt < 2; mt++)
#pragma unroll
        for (int nt = 0; nt < 8; nt++) {
            int c0 = nwBase + nt * 8 + 2 * tg;
            float bb0 = sm_b4[c0], bb1 = sm_b4[c0 + 1];
            int rlo = rowBase + mr + mt * 16 + g;
            *(float2*)(out + (size_t)rlo * DD + c0) = make_float2(acc[mt][nt][0] + bb0, acc[mt][nt][1] + bb1);
            *(float2*)(out + (size_t)(rlo + 8) * DD + c0) = make_float2(acc[mt][nt][2] + bb0, acc[mt][nt][3] + bb1);
        }
}

// ---------------- host side: stream/events created once at load ----------------
struct HostCtx {
    cudaStream_t s2;
    cudaEvent_t evStart, evTable, evSide;
    HostCtx() {
        cudaStreamCreateWithFlags(&s2, cudaStreamNonBlocking);
        cudaEventCreateWithFlags(&evStart, cudaEventDisableTiming);
        cudaEventCreateWithFlags(&evTable, cudaEventDisableTiming);
        cudaEventCreateWithFlags(&evSide, cudaEventDisableTiming);
    }
};
static HostCtx g_ctx;

extern "C" void kernel_launch(void* const* d_in, const int* in_sizes, int n_in,
                              void* d_out, int out_size) {
    const float* x = (const float*)d_in[0];
    const float* h = (const float*)d_in[1];
    const void* ei = d_in[2];
    int base = (in_sizes[3] == 1) ? 4 : 3;
    const float* W1 = (const float*)d_in[base + 0];
    const float* b1 = (const float*)d_in[base + 1];
    const float* W2 = (const float*)d_in[base + 2];
    const float* b2 = (const float*)d_in[base + 3];
    const float* W3 = (const float*)d_in[base + 4];
    const float* b3 = (const float*)d_in[base + 5];
    const float* ga = (const float*)d_in[base + 6];
    const float* be = (const float*)d_in[base + 7];
    const float* W4 = (const float*)d_in[base + 8];
    const float* b4 = (const float*)d_in[base + 9];
    float* out = (float*)d_out;

    const int E = in_sizes[2] / 2;

    cudaFuncSetAttribute(node_kernel, cudaFuncAttributeMaxDynamicSharedMemorySize, SMEM_NODE);

    // fork side stream
    cudaEventRecord(g_ctx.evStart, 0);
    cudaStreamWaitEvent(g_ctx.s2, g_ctx.evStart, 0);

    // side stream: table (writes fp16 pairs) -> evTable -> wsplit -> evSide
    table_kernel<<<TABP / 32, 128, 0, g_ctx.s2>>>(W1, b1, W2, b2);
    cudaEventRecord(g_ctx.evTable, g_ctx.s2);
    wsplit_kernel<<<(256 * 256 + 128 * 256 + 255) / 256, 256, 0, g_ctx.s2>>>(W3, W4);
    cudaEventRecord(g_ctx.evSide, g_ctx.s2);

    // main stream: zero(+detect+h16) -> [table] -> edge (4 edges/warp) -> [wsplit] -> node
    zero_kernel<<<512, 256>>>((const int*)ei, h);
    cudaStreamWaitEvent(0, g_ctx.evTable, 0);
    int edge_warps = (E + 3) / 4;
    int edge_blocks = (edge_warps * 32 + 255) / 256;
    edge_kernel<<<edge_blocks, 256>>>(x, ei, E);
    cudaStreamWaitEvent(0, g_ctx.evSide, 0);
    node_kernel<<<NODES / 128, 256, SMEM_NODE>>>(h, b3, ga, be, b4, out);

    (void)n_in; (void)out_size;
}

// round 16
// speedup vs baseline: 1.0139x; 1.0139x over previous
#include <cuda_runtime.h>
#include <cuda_bf16.h>
#include <cuda_fp16.h>
#include <math.h>
#include <cstdint>

#define PB 8
#define NNODES_PER_B 2048
#define DD 128
#define HH 256
#define NODES (PB * NNODES_PER_B)   // 16384
#define TABP 4096
#define TABR 16.0f

// ---------------- device scratch ----------------
__device__ __align__(16) __half2 g_tableP[TABP * DD]; // 2 MB paired fp16 (f_i, f_{i+1})
__device__ __align__(16) __half2 g_hh[NODES * 64];    // 4 MB fp16 copy of h (edge gather only)
__device__ __align__(16) float4 g_x4[NODES];          // 256 KB packed coordinates
__device__ float g_sums[NODES * DD];                  // 8 MB scatter-sum
__device__ float g_cnt[NODES];
__device__ int   g_oddOr;
__device__ __align__(16) __nv_bfloat16 g_w3h[256 * 256];
__device__ __align__(16) __nv_bfloat16 g_w3l[256 * 256];
__device__ __align__(16) __nv_bfloat16 g_w4h[128 * 256];
__device__ __align__(16) __nv_bfloat16 g_w4l[128 * 256];

// ---------------- kernel 1: zero scratch + detect edge dtype + h->fp16 + pack x ----------------
__global__ void zero_kernel(const int* __restrict__ ei, const float* __restrict__ h,
                            const float* __restrict__ x) {
    int idx = blockIdx.x * blockDim.x + threadIdx.x;
    int stride = gridDim.x * blockDim.x;
    float4 z = make_float4(0.f, 0.f, 0.f, 0.f);
    const int n4 = (NODES * DD) / 4;
    for (int i = idx; i < n4; i += stride) ((float4*)g_sums)[i] = z;
    const int c4 = NODES / 4;
    for (int i = idx; i < c4; i += stride) ((float4*)g_cnt)[i] = z;
    const int nh2 = NODES * 64;
    for (int i = idx; i < nh2; i += stride) {
        float2 v = ((const float2*)h)[i];
        g_hh[i] = __floats2half2_rn(v.x, v.y);
    }
    for (int i = idx; i < NODES; i += stride) {
        g_x4[i] = make_float4(x[i * 3 + 0], x[i * 3 + 1], x[i * 3 + 2], 0.f);
    }
    if (blockIdx.x == 0) {
        if (threadIdx.x == 0) g_oddOr = 0;
        __syncthreads();
        int acc = 0;
        for (int k = threadIdx.x; k < 2048; k += blockDim.x) acc |= ei[2 * k + 1];
        if (acc) atomicOr(&g_oddOr, acc);
    }
}

// ---------------- kernel 3: build filter table, write fp16 pairs directly ----------------
__global__ void table_kernel(const float* __restrict__ W1, const float* __restrict__ b1,
                             const float* __restrict__ W2, const float* __restrict__ b2) {
    __shared__ float s[36 * 256];
    const int tid = threadIdx.x;
    const int pBase = blockIdx.x * 32;
    const float delta = TABR / (float)(TABP - 1);

    for (int idx = tid; idx < 33 * 256; idx += 128) {
        int j = idx / 33, p = idx - j * 33;
        int pt = pBase + p;
        if (pt > TABP - 1) pt = TABP - 1;
        float t = (float)pt * delta;
        float a = t * W1[j] + b1[j];
        s[j * 36 + p] = a / (1.0f + __expf(-a));
    }
    __syncthreads();

    const int d = tid;   // 0..127
    float acc[33];
#pragma unroll
    for (int p = 0; p < 33; p++) acc[p] = 0.f;

    for (int j = 0; j < 256; j++) {
        float w = W2[j * DD + d];
        const float4* sp = (const float4*)(s + j * 36);
#pragma unroll
        for (int q = 0; q < 8; q++) {
            float4 sv = sp[q];
            acc[4 * q + 0] += sv.x * w; acc[4 * q + 1] += sv.y * w;
            acc[4 * q + 2] += sv.z * w; acc[4 * q + 3] += sv.w * w;
        }
        acc[32] += s[j * 36 + 32] * w;
    }
    float bb = b2[d];
#pragma unroll
    for (int p = 0; p < 32; p++)
        g_tableP[(size_t)(pBase + p) * DD + d] = __floats2half2_rn(acc[p] + bb, acc[p + 1] + bb);
}

// ---------------- kernel 3b: split weights (transposed [N][K], bf16 hi/lo) ----------------
__global__ void wsplit_kernel(const float* __restrict__ W3, const float* __restrict__ W4) {
    int idx = blockIdx.x * blockDim.x + threadIdx.x;
    if (idx < 256 * 256) {
        int n = idx >> 8, k = idx & 255;
        float v = W3[k * 256 + n];
        __nv_bfloat16 hi = __float2bfloat16_rn(v);
        g_w3h[idx] = hi;
        g_w3l[idx] = __float2bfloat16_rn(v - __bfloat162float(hi));
    } else if (idx < 256 * 256 + 128 * 256) {
        int j = idx - 256 * 256;
        int n = j >> 8, k = j & 255;
        float v = W4[k * 128 + n];
        __nv_bfloat16 hi = __float2bfloat16_rn(v);
        g_w4h[j] = hi;
        g_w4l[j] = __float2bfloat16_rn(v - __bfloat162float(hi));
    }
}

// ---------------- kernel 4: edge kernel, 2 edges per warp (R14 winner) + packed x ----------------
// Half-warp (16 lanes) per edge; lane covers dims {4*l..4*l+3} and {64+4*l..64+4*l+3}.
__global__ void edge_kernel(const void* __restrict__ eiv, int E) {
    int gt = blockIdx.x * blockDim.x + threadIdx.x;
    int e = (gt >> 5) * 2 + ((threadIdx.x >> 4) & 1);
    int l = threadIdx.x & 15;          // lane within half-warp
    if (e >= E) return;

    int row, col;
    if (g_oddOr == 0) {
        const long long* p = (const long long*)eiv;
        row = (int)p[e]; col = (int)p[E + e];
    } else {
        const int* p = (const int*)eiv;
        row = p[e]; col = p[E + e];
    }
    float4 xr = g_x4[row];
    float4 xc = g_x4[col];
    float dx = xr.x - xc.x;
    float dy = xr.y - xc.y;
    float dz = xr.z - xc.z;
    float dist = sqrtf(dx * dx + dy * dy + dz * dz);
    float t = dist * ((float)(TABP - 1) / TABR);
    int i0 = (int)t;
    if (i0 > TABP - 2) i0 = TABP - 2;
    float fr = t - (float)i0;

    // table row: 32 uint4; lane takes idx l (dims 4l..) and l+16 (dims 64+4l..)
    const uint4* tp = (const uint4*)(g_tableP + (size_t)i0 * DD);
    uint4 pv0 = tp[l];
    uint4 pv1 = tp[l + 16];
    // h row: 32 uint2; lane takes idx l and l+16
    const uint2* hp = (const uint2*)(g_hh + (size_t)col * 64);
    uint2 h0 = hp[l];
    uint2 h1 = hp[l + 16];

    float2 a0 = __half22float2(*(const __half2*)&pv0.x);
    float2 a1 = __half22float2(*(const __half2*)&pv0.y);
    float2 a2 = __half22float2(*(const __half2*)&pv0.z);
    float2 a3 = __half22float2(*(const __half2*)&pv0.w);
    float2 b0 = __half22float2(*(const __half2*)&pv1.x);
    float2 b1 = __half22float2(*(const __half2*)&pv1.y);
    float2 b2 = __half22float2(*(const __half2*)&pv1.z);
    float2 b3 = __half22float2(*(const __half2*)&pv1.w);
    float2 ha0 = __half22float2(*(const __half2*)&h0.x);
    float2 ha1 = __half22float2(*(const __half2*)&h0.y);
    float2 hb0 = __half22float2(*(const __half2*)&h1.x);
    float2 hb1 = __half22float2(*(const __half2*)&h1.y);

    float m0 = ha0.x * (a0.x + fr * (a0.y - a0.x));
    float m1 = ha0.y * (a1.x + fr * (a1.y - a1.x));
    float m2 = ha1.x * (a2.x + fr * (a2.y - a2.x));
    float m3 = ha1.y * (a3.x + fr * (a3.y - a3.x));
    float n0 = hb0.x * (b0.x + fr * (b0.y - b0.x));
    float n1 = hb0.y * (b1.x + fr * (b1.y - b1.x));
    float n2 = hb1.x * (b2.x + fr * (b2.y - b2.x));
    float n3 = hb1.y * (b3.x + fr * (b3.y - b3.x));

    float* dst = g_sums + (size_t)row * DD;
    asm volatile("red.global.add.v4.f32 [%0], {%1, %2, %3, %4};"
                 :: "l"(dst + l * 4), "f"(m0), "f"(m1), "f"(m2), "f"(m3) : "memory");
    asm volatile("red.global.add.v4.f32 [%0], {%1, %2, %3, %4};"
                 :: "l"(dst + 64 + l * 4), "f"(n0), "f"(n1), "f"(n2), "f"(n3) : "memory");
    if (l == 0)
        asm volatile("red.global.add.f32 [%0], %1;" :: "l"(&g_cnt[row]), "f"(1.0f) : "memory");
}

// ---------------- node MLP machinery (R4 verbatim — CONVERGED, do not touch) ----------------
#define PADW 132                        // u32 words per padded row (264 bf16, 528B)
#define OFF_ALO (128 * PADW)
#define OFF_B   (2 * 128 * PADW)
#define SM_U32  (3 * 128 * PADW)        // 202752 B
#define SMEM_NODE (202752 + 1024 * 3 + 512 + 1024 * 2)

__device__ __forceinline__ void mma_bf16(float* c, const uint32_t* a, uint32_t b0, uint32_t b1) {
    asm volatile("mma.sync.aligned.m16n8k16.row.col.f32.bf16.bf16.f32 "
                 "{%0,%1,%2,%3}, {%4,%5,%6,%7}, {%8,%9}, {%0,%1,%2,%3};"
                 : "+f"(c[0]), "+f"(c[1]), "+f"(c[2]), "+f"(c[3])
                 : "r"(a[0]), "r"(a[1]), "r"(a[2]), "r"(a[3]), "r"(b0), "r"(b1));
}
__device__ __forceinline__ uint32_t pack_split(float v0, float v1, uint32_t& lo) {
    __nv_bfloat16 h0 = __float2bfloat16_rn(v0);
    __nv_bfloat16 h1 = __float2bfloat16_rn(v1);
    __nv_bfloat16 l0 = __float2bfloat16_rn(v0 - __bfloat162float(h0));
    __nv_bfloat16 l1 = __float2bfloat16_rn(v1 - __bfloat162float(h1));
    lo = ((uint32_t)__bfloat16_as_ushort(l1) << 16) | __bfloat16_as_ushort(l0);
    return ((uint32_t)__bfloat16_as_ushort(h1) << 16) | __bfloat16_as_ushort(h0);
}

template <int NTBASE>
__device__ __forceinline__ void gemm_pass(const uint32_t* __restrict__ Asm,
                                          const uint32_t* __restrict__ Bsm,
                                          float (&acc)[2][16][4],
                                          int mr, int nwBase, int g, int tg) {
    for (int ks = 0; ks < 16; ks++) {
        uint32_t a[2][4];
#pragma unroll
        for (int mt = 0; mt < 2; mt++) {
            int w = (mr + mt * 16 + g) * PADW + ks * 8 + tg;
            a[mt][0] = Asm[w];
            a[mt][1] = Asm[w + 8 * PADW];
            a[mt][2] = Asm[w + 4];
            a[mt][3] = Asm[w + 8 * PADW + 4];
        }
#pragma unroll
        for (int nt = 0; nt < 8; nt++) {
            int bw = (nwBase + nt * 8 + g) * PADW + ks * 8 + tg;
            uint32_t b0 = Bsm[bw], b1 = Bsm[bw + 4];
            mma_bf16(acc[0][NTBASE + nt], a[0], b0, b1);
            mma_bf16(acc[1][NTBASE + nt], a[1], b0, b1);
        }
    }
}

__device__ __forceinline__ void load_b128(uint4* __restrict__ dstB,
                                          const uint4* __restrict__ src, int nOff) {
    for (int i = threadIdx.x; i < 128 * 32; i += 256) {
        int nl = i >> 5, k4 = i & 31;
        dstB[nl * 33 + k4] = src[(nOff + nl) * 32 + k4];
    }
}

__global__ void __launch_bounds__(256, 1)
node_kernel(const float* __restrict__ h,
            const float* __restrict__ b3, const float* __restrict__ gamma,
            const float* __restrict__ beta, const float* __restrict__ b4,
            float* __restrict__ out) {
    extern __shared__ uint32_t sm[];
    uint32_t* Ahi = sm;
    uint32_t* Alo = sm + OFF_ALO;
    uint32_t* Bsm = sm + OFF_B;
    float* sm_b3 = (float*)(sm + SM_U32);
    float* sm_ga = sm_b3 + 256;
    float* sm_be = sm_ga + 256;
    float* sm_b4 = sm_be + 256;
    float* sm_s1 = sm_b4 + 128;
    float* sm_s2 = sm_s1 + 256;

    const int tid = threadIdx.x;
    const int lane = tid & 31;
    const int wid = tid >> 5;
    const int g = lane >> 2, tg = lane & 3;
    const int mw = wid & 3, nw = wid >> 2;
    const int mr = mw * 32, nwBase = nw * 64;
    const int rowBase = blockIdx.x * 128;

    sm_b3[tid] = b3[tid];
    sm_ga[tid] = gamma[tid];
    sm_be[tid] = beta[tid];
    if (tid < 128) sm_b4[tid] = b4[tid];

    // ---- build A = [h | agg], split hi/lo ----
    for (int idx = tid; idx < 128 * 64; idx += 256) {
        int row = idx >> 6, kp = idx & 63;
        float2 v = ((const float2*)(h + (size_t)(rowBase + row) * DD))[kp];
        uint32_t lo, hi = pack_split(v.x, v.y, lo);
        Ahi[row * PADW + kp] = hi;
        Alo[row * PADW + kp] = lo;
    }
    for (int idx = tid; idx < 128 * 64; idx += 256) {
        int row = idx >> 6, kp = idx & 63;
        int node = rowBase + row;
        float inv = 1.0f / fmaxf(g_cnt[node], 1.0f);
        float2 v = ((const float2*)(g_sums + (size_t)node * DD))[kp];
        uint32_t lo, hi = pack_split(v.x * inv, v.y * inv, lo);
        Ahi[row * PADW + 64 + kp] = hi;
        Alo[row * PADW + 64 + kp] = lo;
    }

    float acc[2][16][4];
#pragma unroll
    for (int mt = 0; mt < 2; mt++)
#pragma unroll
        for (int nt = 0; nt < 16; nt++)
#pragma unroll
            for (int f = 0; f < 4; f++) acc[mt][nt][f] = 0.f;

    // ---- GEMM1: 2 col-chunks; hi*hi + lo*hi + hi*lo ----
#pragma unroll
    for (int chunk = 0; chunk < 2; chunk++) {
        __syncthreads();
        load_b128((uint4*)Bsm, (const uint4*)g_w3h, chunk * 128);
        __syncthreads();
        if (chunk == 0) {
            gemm_pass<0>(Ahi, Bsm, acc, mr, nwBase, g, tg);
            gemm_pass<0>(Alo, Bsm, acc, mr, nwBase, g, tg);
        } else {
            gemm_pass<8>(Ahi, Bsm, acc, mr, nwBase, g, tg);
            gemm_pass<8>(Alo, Bsm, acc, mr, nwBase, g, tg);
        }
        __syncthreads();
        load_b128((uint4*)Bsm, (const uint4*)g_w3l, chunk * 128);
        __syncthreads();
        if (chunk == 0) gemm_pass<0>(Ahi, Bsm, acc, mr, nwBase, g, tg);
        else            gemm_pass<8>(Ahi, Bsm, acc, mr, nwBase, g, tg);
    }
    __syncthreads();

    // ---- epilogue 1: +b3, LayerNorm, SiLU, re-split into A buffers ----
    float s1[4] = {0.f, 0.f, 0.f, 0.f}, s2[4] = {0.f, 0.f, 0.f, 0.f};
#pragma unroll
    for (int mt = 0; mt < 2; mt++)
#pragma unroll
        for (int q = 0; q < 16; q++) {
            int chunk = q >> 3, nt = q & 7;
            int c0 = chunk * 128 + nwBase + nt * 8 + 2 * tg;
            float u0 = acc[mt][q][0] + sm_b3[c0];
            float u1 = acc[mt][q][1] + sm_b3[c0 + 1];
            float u2 = acc[mt][q][2] + sm_b3[c0];
            float u3 = acc[mt][q][3] + sm_b3[c0 + 1];
            acc[mt][q][0] = u0; acc[mt][q][1] = u1;
            acc[mt][q][2] = u2; acc[mt][q][3] = u3;
            s1[mt * 2 + 0] += u0 + u1;  s2[mt * 2 + 0] += u0 * u0 + u1 * u1;
            s1[mt * 2 + 1] += u2 + u3;  s2[mt * 2 + 1] += u2 * u2 + u3 * u3;
        }
#pragma unroll
    for (int r = 0; r < 4; r++) {
#pragma unroll
        for (int off = 1; off < 4; off <<= 1) {
            s1[r] += __shfl_xor_sync(0xffffffffu, s1[r], off);
            s2[r] += __shfl_xor_sync(0xffffffffu, s2[r], off);
        }
    }
    if (tg == 0) {
        int rows[4] = {mr + g, mr + g + 8, mr + 16 + g, mr + 24 + g};
#pragma unroll
        for (int r = 0; r < 4; r++) {
            sm_s1[rows[r] * 2 + nw] = s1[r];
            sm_s2[rows[r] * 2 + nw] = s2[r];
        }
    }
    __syncthreads();
    float mu[4], rs[4];
    {
        int rows[4] = {mr + g, mr + g + 8, mr + 16 + g, mr + 24 + g};
#pragma unroll
        for (int r = 0; r < 4; r++) {
            float S1 = sm_s1[rows[r] * 2] + sm_s1[rows[r] * 2 + 1];
            float S2 = sm_s2[rows[r] * 2] + sm_s2[rows[r] * 2 + 1];
            float m = S1 * (1.0f / 256.0f);
            float var = S2 * (1.0f / 256.0f) - m * m;
            mu[r] = m;
            rs[r] = rsqrtf(var + 1e-5f);
        }
    }
    __syncthreads();
#pragma unroll
    for (int mt = 0; mt < 2; mt++)
#pragma unroll
        for (int q = 0; q < 16; q++) {
            int chunk = q >> 3, nt = q & 7;
            int c0 = chunk * 128 + nwBase + nt * 8 + 2 * tg;
            float ga0 = sm_ga[c0], ga1 = sm_ga[c0 + 1];
            float be0 = sm_be[c0], be1 = sm_be[c0 + 1];
            int rlo = mr + mt * 16 + g;
            {
                float v0 = (acc[mt][q][0] - mu[mt * 2]) * rs[mt * 2] * ga0 + be0;
                float v1 = (acc[mt][q][1] - mu[mt * 2]) * rs[mt * 2] * ga1 + be1;
                float w0 = v0 / (1.0f + __expf(-v0));
                float w1 = v1 / (1.0f + __expf(-v1));
                uint32_t lo, hi = pack_split(w0, w1, lo);
                int word = rlo * PADW + (c0 >> 1);
                Ahi[word] = hi; Alo[word] = lo;
            }
            {
                float v0 = (acc[mt][q][2] - mu[mt * 2 + 1]) * rs[mt * 2 + 1] * ga0 + be0;
                float v1 = (acc[mt][q][3] - mu[mt * 2 + 1]) * rs[mt * 2 + 1] * ga1 + be1;
                float w0 = v0 / (1.0f + __expf(-v0));
                float w1 = v1 / (1.0f + __expf(-v1));
                uint32_t lo, hi = pack_split(w0, w1, lo);
                int word = (rlo + 8) * PADW + (c0 >> 1);
                Ahi[word] = hi; Alo[word] = lo;
            }
        }

    // ---- GEMM2: C2(128x128) = A2 @ W4T^T ----
#pragma unroll
    for (int mt = 0; mt < 2; mt++)
#pragma unroll
        for (int nt = 0; nt < 8; nt++)
#pragma unroll
            for (int f = 0; f < 4; f++) acc[mt][nt][f] = 0.f;

    __syncthreads();
    load_b128((uint4*)Bsm, (const uint4*)g_w4h, 0);
    __syncthreads();
    gemm_pass<0>(Ahi, Bsm, acc, mr, nwBase, g, tg);
    gemm_pass<0>(Alo, Bsm, acc, mr, nwBase, g, tg);
    __syncthreads();
    load_b128((uint4*)Bsm, (const uint4*)g_w4l, 0);
    __syncthreads();
    gemm_pass<0>(Ahi, Bsm, acc, mr, nwBase, g, tg);

    // ---- epilogue 2: +b4, store ----
#pragma unroll
    for (int mt = 0; mt < 2; mt++)
#pragma unroll
        for (int nt = 0; nt < 8; nt++) {
            int c0 = nwBase + nt * 8 + 2 * tg;
            float bb0 = sm_b4[c0], bb1 = sm_b4[c0 + 1];
            int rlo = rowBase + mr + mt * 16 + g;
            *(float2*)(out + (size_t)rlo * DD + c0) = make_float2(acc[mt][nt][0] + bb0, acc[mt][nt][1] + bb1);
            *(float2*)(out + (size_t)(rlo + 8) * DD + c0) = make_float2(acc[mt][nt][2] + bb0, acc[mt][nt][3] + bb1);
        }
}

// ---------------- host side: stream/events created once at load ----------------
struct HostCtx {
    cudaStream_t s2;
    cudaEvent_t evStart, evTable, evSide;
    HostCtx() {
        cudaStreamCreateWithFlags(&s2, cudaStreamNonBlocking);
        cudaEventCreateWithFlags(&evStart, cudaEventDisableTiming);
        cudaEventCreateWithFlags(&evTable, cudaEventDisableTiming);
        cudaEventCreateWithFlags(&evSide, cudaEventDisableTiming);
    }
};
static HostCtx g_ctx;

extern "C" void kernel_launch(void* const* d_in, const int* in_sizes, int n_in,
                              void* d_out, int out_size) {
    const float* x = (const float*)d_in[0];
    const float* h = (const float*)d_in[1];
    const void* ei = d_in[2];
    int base = (in_sizes[3] == 1) ? 4 : 3;
    const float* W1 = (const float*)d_in[base + 0];
    const float* b1 = (const float*)d_in[base + 1];
    const float* W2 = (const float*)d_in[base + 2];
    const float* b2 = (const float*)d_in[base + 3];
    const float* W3 = (const float*)d_in[base + 4];
    const float* b3 = (const float*)d_in[base + 5];
    const float* ga = (const float*)d_in[base + 6];
    const float* be = (const float*)d_in[base + 7];
    const float* W4 = (const float*)d_in[base + 8];
    const float* b4 = (const float*)d_in[base + 9];
    float* out = (float*)d_out;

    const int E = in_sizes[2] / 2;

    cudaFuncSetAttribute(node_kernel, cudaFuncAttributeMaxDynamicSharedMemorySize, SMEM_NODE);

    // fork side stream
    cudaEventRecord(g_ctx.evStart, 0);
    cudaStreamWaitEvent(g_ctx.s2, g_ctx.evStart, 0);

    // side stream: table (writes fp16 pairs) -> evTable -> wsplit -> evSide
    table_kernel<<<TABP / 32, 128, 0, g_ctx.s2>>>(W1, b1, W2, b2);
    cudaEventRecord(g_ctx.evTable, g_ctx.s2);
    wsplit_kernel<<<(256 * 256 + 128 * 256 + 255) / 256, 256, 0, g_ctx.s2>>>(W3, W4);
    cudaEventRecord(g_ctx.evSide, g_ctx.s2);

    // main stream: zero(+detect+h16+x4) -> [table] -> edge (2 edges/warp) -> [wsplit] -> node
    zero_kernel<<<512, 256>>>((const int*)ei, h, x);
    cudaStreamWaitEvent(0, g_ctx.evTable, 0);
    int edge_warps = (E + 1) / 2;
    int edge_blocks = (edge_warps * 32 + 255) / 256;
    edge_kernel<<<edge_blocks, 256>>>(ei, E);
    cudaStreamWaitEvent(0, g_ctx.evSide, 0);
    node_kernel<<<NODES / 128, 256, SMEM_NODE>>>(h, b3, ga, be, b4, out);

    (void)n_in; (void)out_size;
}

// round 17
// speedup vs baseline: 1.0261x; 1.0120x over previous
#include <cuda_runtime.h>
#include <cuda_bf16.h>
#include <cuda_fp16.h>
#include <math.h>
#include <cstdint>

#define PB 8
#define NNODES_PER_B 2048
#define DD 128
#define HH 256
#define NODES (PB * NNODES_PER_B)   // 16384
#define TABP 2048
#define TABR 16.0f

// ---------------- device scratch ----------------
__device__ __align__(16) __half2 g_tableP[TABP * DD]; // 1 MB paired fp16 (f_i, f_{i+1})
__device__ __align__(16) __half2 g_hh[NODES * 64];    // 4 MB fp16 copy of h (edge gather only)
__device__ __align__(16) float4 g_x4[NODES];          // 256 KB packed coordinates
__device__ float g_sums[NODES * DD];                  // 8 MB scatter-sum
__device__ float g_cnt[NODES];
__device__ int   g_oddOr;
__device__ __align__(16) __nv_bfloat16 g_w3h[256 * 256];
__device__ __align__(16) __nv_bfloat16 g_w3l[256 * 256];
__device__ __align__(16) __nv_bfloat16 g_w4h[128 * 256];
__device__ __align__(16) __nv_bfloat16 g_w4l[128 * 256];

// ---------------- kernel 1: zero scratch + detect edge dtype + h->fp16 + pack x ----------------
__global__ void zero_kernel(const int* __restrict__ ei, const float* __restrict__ h,
                            const float* __restrict__ x) {
    int idx = blockIdx.x * blockDim.x + threadIdx.x;
    int stride = gridDim.x * blockDim.x;
    float4 z = make_float4(0.f, 0.f, 0.f, 0.f);
    const int n4 = (NODES * DD) / 4;
    for (int i = idx; i < n4; i += stride) ((float4*)g_sums)[i] = z;
    const int c4 = NODES / 4;
    for (int i = idx; i < c4; i += stride) ((float4*)g_cnt)[i] = z;
    const int nh2 = NODES * 64;
    for (int i = idx; i < nh2; i += stride) {
        float2 v = ((const float2*)h)[i];
        g_hh[i] = __floats2half2_rn(v.x, v.y);
    }
    for (int i = idx; i < NODES; i += stride) {
        g_x4[i] = make_float4(x[i * 3 + 0], x[i * 3 + 1], x[i * 3 + 2], 0.f);
    }
    if (blockIdx.x == 0) {
        if (threadIdx.x == 0) g_oddOr = 0;
        __syncthreads();
        int acc = 0;
        for (int k = threadIdx.x; k < 2048; k += blockDim.x) acc |= ei[2 * k + 1];
        if (acc) atomicOr(&g_oddOr, acc);
    }
}

// ---------------- kernel 3: build filter table, write fp16 pairs directly ----------------
__global__ void table_kernel(const float* __restrict__ W1, const float* __restrict__ b1,
                             const float* __restrict__ W2, const float* __restrict__ b2) {
    __shared__ float s[36 * 256];
    const int tid = threadIdx.x;
    const int pBase = blockIdx.x * 32;
    const float delta = TABR / (float)(TABP - 1);

    for (int idx = tid; idx < 33 * 256; idx += 128) {
        int j = idx / 33, p = idx - j * 33;
        int pt = pBase + p;
        if (pt > TABP - 1) pt = TABP - 1;
        float t = (float)pt * delta;
        float a = t * W1[j] + b1[j];
        s[j * 36 + p] = a / (1.0f + __expf(-a));
    }
    __syncthreads();

    const int d = tid;   // 0..127
    float acc[33];
#pragma unroll
    for (int p = 0; p < 33; p++) acc[p] = 0.f;

    for (int j = 0; j < 256; j++) {
        float w = W2[j * DD + d];
        const float4* sp = (const float4*)(s + j * 36);
#pragma unroll
        for (int q = 0; q < 8; q++) {
            float4 sv = sp[q];
            acc[4 * q + 0] += sv.x * w; acc[4 * q + 1] += sv.y * w;
            acc[4 * q + 2] += sv.z * w; acc[4 * q + 3] += sv.w * w;
        }
        acc[32] += s[j * 36 + 32] * w;
    }
    float bb = b2[d];
#pragma unroll
    for (int p = 0; p < 32; p++)
        g_tableP[(size_t)(pBase + p) * DD + d] = __floats2half2_rn(acc[p] + bb, acc[p + 1] + bb);
}

// ---------------- kernel 3b: split weights (transposed [N][K], bf16 hi/lo) ----------------
__global__ void wsplit_kernel(const float* __restrict__ W3, const float* __restrict__ W4) {
    int idx = blockIdx.x * blockDim.x + threadIdx.x;
    if (idx < 256 * 256) {
        int n = idx >> 8, k = idx & 255;
        float v = W3[k * 256 + n];
        __nv_bfloat16 hi = __float2bfloat16_rn(v);
        g_w3h[idx] = hi;
        g_w3l[idx] = __float2bfloat16_rn(v - __bfloat162float(hi));
    } else if (idx < 256 * 256 + 128 * 256) {
        int j = idx - 256 * 256;
        int n = j >> 8, k = j & 255;
        float v = W4[k * 128 + n];
        __nv_bfloat16 hi = __float2bfloat16_rn(v);
        g_w4h[j] = hi;
        g_w4l[j] = __float2bfloat16_rn(v - __bfloat162float(hi));
    }
}

// ---------------- kernel 4: edge kernel, 2 edges per warp + packed x ----------------
// Half-warp (16 lanes) per edge; lane covers dims {4*l..4*l+3} and {64+4*l..64+4*l+3}.
__global__ void edge_kernel(const void* __restrict__ eiv, int E) {
    int gt = blockIdx.x * blockDim.x + threadIdx.x;
    int e = (gt >> 5) * 2 + ((threadIdx.x >> 4) & 1);
    int l = threadIdx.x & 15;          // lane within half-warp
    if (e >= E) return;

    int row, col;
    if (g_oddOr == 0) {
        const long long* p = (const long long*)eiv;
        row = (int)p[e]; col = (int)p[E + e];
    } else {
        const int* p = (const int*)eiv;
        row = p[e]; col = p[E + e];
    }
    float4 xr = g_x4[row];
    float4 xc = g_x4[col];
    float dx = xr.x - xc.x;
    float dy = xr.y - xc.y;
    float dz = xr.z - xc.z;
    float dist = sqrtf(dx * dx + dy * dy + dz * dz);
    float t = dist * ((float)(TABP - 1) / TABR);
    int i0 = (int)t;
    if (i0 > TABP - 2) i0 = TABP - 2;
    float fr = t - (float)i0;

    const uint4* tp = (const uint4*)(g_tableP + (size_t)i0 * DD);
    uint4 pv0 = tp[l];
    uint4 pv1 = tp[l + 16];
    const uint2* hp = (const uint2*)(g_hh + (size_t)col * 64);
    uint2 h0 = hp[l];
    uint2 h1 = hp[l + 16];

    float2 a0 = __half22float2(*(const __half2*)&pv0.x);
    float2 a1 = __half22float2(*(const __half2*)&pv0.y);
    float2 a2 = __half22float2(*(const __half2*)&pv0.z);
    float2 a3 = __half22float2(*(const __half2*)&pv0.w);
    float2 b0 = __half22float2(*(const __half2*)&pv1.x);
    float2 b1 = __half22float2(*(const __half2*)&pv1.y);
    float2 b2 = __half22float2(*(const __half2*)&pv1.z);
    float2 b3 = __half22float2(*(const __half2*)&pv1.w);
    float2 ha0 = __half22float2(*(const __half2*)&h0.x);
    float2 ha1 = __half22float2(*(const __half2*)&h0.y);
    float2 hb0 = __half22float2(*(const __half2*)&h1.x);
    float2 hb1 = __half22float2(*(const __half2*)&h1.y);

    float m0 = ha0.x * (a0.x + fr * (a0.y - a0.x));
    float m1 = ha0.y * (a1.x + fr * (a1.y - a1.x));
    float m2 = ha1.x * (a2.x + fr * (a2.y - a2.x));
    float m3 = ha1.y * (a3.x + fr * (a3.y - a3.x));
    float n0 = hb0.x * (b0.x + fr * (b0.y - b0.x));
    float n1 = hb0.y * (b1.x + fr * (b1.y - b1.x));
    float n2 = hb1.x * (b2.x + fr * (b2.y - b2.x));
    float n3 = hb1.y * (b3.x + fr * (b3.y - b3.x));

    float* dst = g_sums + (size_t)row * DD;
    asm volatile("red.global.add.v4.f32 [%0], {%1, %2, %3, %4};"
                 :: "l"(dst + l * 4), "f"(m0), "f"(m1), "f"(m2), "f"(m3) : "memory");
    asm volatile("red.global.add.v4.f32 [%0], {%1, %2, %3, %4};"
                 :: "l"(dst + 64 + l * 4), "f"(n0), "f"(n1), "f"(n2), "f"(n3) : "memory");
    if (l == 0)
        asm volatile("red.global.add.f32 [%0], %1;" :: "l"(&g_cnt[row]), "f"(1.0f) : "memory");
}

// ---------------- node MLP machinery (R4 verbatim — CONVERGED, do not touch) ----------------
#define PADW 132                        // u32 words per padded row (264 bf16, 528B)
#define OFF_ALO (128 * PADW)
#define OFF_B   (2 * 128 * PADW)
#define SM_U32  (3 * 128 * PADW)        // 202752 B
#define SMEM_NODE (202752 + 1024 * 3 + 512 + 1024 * 2)

__device__ __forceinline__ void mma_bf16(float* c, const uint32_t* a, uint32_t b0, uint32_t b1) {
    asm volatile("mma.sync.aligned.m16n8k16.row.col.f32.bf16.bf16.f32 "
                 "{%0,%1,%2,%3}, {%4,%5,%6,%7}, {%8,%9}, {%0,%1,%2,%3};"
                 : "+f"(c[0]), "+f"(c[1]), "+f"(c[2]), "+f"(c[3])
                 : "r"(a[0]), "r"(a[1]), "r"(a[2]), "r"(a[3]), "r"(b0), "r"(b1));
}
__device__ __forceinline__ uint32_t pack_split(float v0, float v1, uint32_t& lo) {
    __nv_bfloat16 h0 = __float2bfloat16_rn(v0);
    __nv_bfloat16 h1 = __float2bfloat16_rn(v1);
    __nv_bfloat16 l0 = __float2bfloat16_rn(v0 - __bfloat162float(h0));
    __nv_bfloat16 l1 = __float2bfloat16_rn(v1 - __bfloat162float(h1));
    lo = ((uint32_t)__bfloat16_as_ushort(l1) << 16) | __bfloat16_as_ushort(l0);
    return ((uint32_t)__bfloat16_as_ushort(h1) << 16) | __bfloat16_as_ushort(h0);
}

template <int NTBASE>
__device__ __forceinline__ void gemm_pass(const uint32_t* __restrict__ Asm,
                                          const uint32_t* __restrict__ Bsm,
                                          float (&acc)[2][16][4],
                                          int mr, int nwBase, int g, int tg) {
    for (int ks = 0; ks < 16; ks++) {
        uint32_t a[2][4];
#pragma unroll
        for (int mt = 0; mt < 2; mt++) {
            int w = (mr + mt * 16 + g) * PADW + ks * 8 + tg;
            a[mt][0] = Asm[w];
            a[mt][1] = Asm[w + 8 * PADW];
            a[mt][2] = Asm[w + 4];
            a[mt][3] = Asm[w + 8 * PADW + 4];
        }
#pragma unroll
        for (int nt = 0; nt < 8; nt++) {
            int bw = (nwBase + nt * 8 + g) * PADW + ks * 8 + tg;
            uint32_t b0 = Bsm[bw], b1 = Bsm[bw + 4];
            mma_bf16(acc[0][NTBASE + nt], a[0], b0, b1);
            mma_bf16(acc[1][NTBASE + nt], a[1], b0, b1);
        }
    }
}

__device__ __forceinline__ void load_b128(uint4* __restrict__ dstB,
                                          const uint4* __restrict__ src, int nOff) {
    for (int i = threadIdx.x; i < 128 * 32; i += 256) {
        int nl = i >> 5, k4 = i & 31;
        dstB[nl * 33 + k4] = src[(nOff + nl) * 32 + k4];
    }
}

__global__ void __launch_bounds__(256, 1)
node_kernel(const float* __restrict__ h,
            const float* __restrict__ b3, const float* __restrict__ gamma,
            const float* __restrict__ beta, const float* __restrict__ b4,
            float* __restrict__ out) {
    extern __shared__ uint32_t sm[];
    uint32_t* Ahi = sm;
    uint32_t* Alo = sm + OFF_ALO;
    uint32_t* Bsm = sm + OFF_B;
    float* sm_b3 = (float*)(sm + SM_U32);
    float* sm_ga = sm_b3 + 256;
    float* sm_be = sm_ga + 256;
    float* sm_b4 = sm_be + 256;
    float* sm_s1 = sm_b4 + 128;
    float* sm_s2 = sm_s1 + 256;

    const int tid = threadIdx.x;
    const int lane = tid & 31;
    const int wid = tid >> 5;
    const int g = lane >> 2, tg = lane & 3;
    const int mw = wid & 3, nw = wid >> 2;
    const int mr = mw * 32, nwBase = nw * 64;
    const int rowBase = blockIdx.x * 128;

    sm_b3[tid] = b3[tid];
    sm_ga[tid] = gamma[tid];
    sm_be[tid] = beta[tid];
    if (tid < 128) sm_b4[tid] = b4[tid];

    // ---- build A = [h | agg], split hi/lo ----
    for (int idx = tid; idx < 128 * 64; idx += 256) {
        int row = idx >> 6, kp = idx & 63;
        float2 v = ((const float2*)(h + (size_t)(rowBase + row) * DD))[kp];
        uint32_t lo, hi = pack_split(v.x, v.y, lo);
        Ahi[row * PADW + kp] = hi;
        Alo[row * PADW + kp] = lo;
    }
    for (int idx = tid; idx < 128 * 64; idx += 256) {
        int row = idx >> 6, kp = idx & 63;
        int node = rowBase + row;
        float inv = 1.0f / fmaxf(g_cnt[node], 1.0f);
        float2 v = ((const float2*)(g_sums + (size_t)node * DD))[kp];
        uint32_t lo, hi = pack_split(v.x * inv, v.y * inv, lo);
        Ahi[row * PADW + 64 + kp] = hi;
        Alo[row * PADW + 64 + kp] = lo;
    }

    float acc[2][16][4];
#pragma unroll
    for (int mt = 0; mt < 2; mt++)
#pragma unroll
        for (int nt = 0; nt < 16; nt++)
#pragma unroll
            for (int f = 0; f < 4; f++) acc[mt][nt][f] = 0.f;

    // ---- GEMM1: 2 col-chunks; hi*hi + lo*hi + hi*lo ----
#pragma unroll
    for (int chunk = 0; chunk < 2; chunk++) {
        __syncthreads();
        load_b128((uint4*)Bsm, (const uint4*)g_w3h, chunk * 128);
        __syncthreads();
        if (chunk == 0) {
            gemm_pass<0>(Ahi, Bsm, acc, mr, nwBase, g, tg);
            gemm_pass<0>(Alo, Bsm, acc, mr, nwBase, g, tg);
        } else {
            gemm_pass<8>(Ahi, Bsm, acc, mr, nwBase, g, tg);
            gemm_pass<8>(Alo, Bsm, acc, mr, nwBase, g, tg);
        }
        __syncthreads();
        load_b128((uint4*)Bsm, (const uint4*)g_w3l, chunk * 128);
        __syncthreads();
        if (chunk == 0) gemm_pass<0>(Ahi, Bsm, acc, mr, nwBase, g, tg);
        else            gemm_pass<8>(Ahi, Bsm, acc, mr, nwBase, g, tg);
    }
    __syncthreads();

    // ---- epilogue 1: +b3, LayerNorm, SiLU, re-split into A buffers ----
    float s1[4] = {0.f, 0.f, 0.f, 0.f}, s2[4] = {0.f, 0.f, 0.f, 0.f};
#pragma unroll
    for (int mt = 0; mt < 2; mt++)
#pragma unroll
        for (int q = 0; q < 16; q++) {
            int chunk = q >> 3, nt = q & 7;
            int c0 = chunk * 128 + nwBase + nt * 8 + 2 * tg;
            float u0 = acc[mt][q][0] + sm_b3[c0];
            float u1 = acc[mt][q][1] + sm_b3[c0 + 1];
            float u2 = acc[mt][q][2] + sm_b3[c0];
            float u3 = acc[mt][q][3] + sm_b3[c0 + 1];
            acc[mt][q][0] = u0; acc[mt][q][1] = u1;
            acc[mt][q][2] = u2; acc[mt][q][3] = u3;
            s1[mt * 2 + 0] += u0 + u1;  s2[mt * 2 + 0] += u0 * u0 + u1 * u1;
            s1[mt * 2 + 1] += u2 + u3;  s2[mt * 2 + 1] += u2 * u2 + u3 * u3;
        }
#pragma unroll
    for (int r = 0; r < 4; r++) {
#pragma unroll
        for (int off = 1; off < 4; off <<= 1) {
            s1[r] += __shfl_xor_sync(0xffffffffu, s1[r], off);
            s2[r] += __shfl_xor_sync(0xffffffffu, s2[r], off);
        }
    }
    if (tg == 0) {
        int rows[4] = {mr + g, mr + g + 8, mr + 16 + g, mr + 24 + g};
#pragma unroll
        for (int r = 0; r < 4; r++) {
            sm_s1[rows[r] * 2 + nw] = s1[r];
            sm_s2[rows[r] * 2 + nw] = s2[r];
        }
    }
    __syncthreads();
    float mu[4], rs[4];
    {
        int rows[4] = {mr + g, mr + g + 8, mr + 16 + g, mr + 24 + g};
#pragma unroll
        for (int r = 0; r < 4; r++) {
            float S1 = sm_s1[rows[r] * 2] + sm_s1[rows[r] * 2 + 1];
            float S2 = sm_s2[rows[r] * 2] + sm_s2[rows[r] * 2 + 1];
            float m = S1 * (1.0f / 256.0f);
            float var = S2 * (1.0f / 256.0f) - m * m;
            mu[r] = m;
            rs[r] = rsqrtf(var + 1e-5f);
        }
    }
    __syncthreads();
#pragma unroll
    for (int mt = 0; mt < 2; mt++)
#pragma unroll
        for (int q = 0; q < 16; q++) {
            int chunk = q >> 3, nt = q & 7;
            int c0 = chunk * 128 + nwBase + nt * 8 + 2 * tg;
            float ga0 = sm_ga[c0], ga1 = sm_ga[c0 + 1];
            float be0 = sm_be[c0], be1 = sm_be[c0 + 1];
            int rlo = mr + mt * 16 + g;
            {
                float v0 = (acc[mt][q][0] - mu[mt * 2]) * rs[mt * 2] * ga0 + be0;
                float v1 = (acc[mt][q][1] - mu[mt * 2]) * rs[mt * 2] * ga1 + be1;
                float w0 = v0 / (1.0f + __expf(-v0));
                float w1 = v1 / (1.0f + __expf(-v1));
                uint32_t lo, hi = pack_split(w0, w1, lo);
                int word = rlo * PADW + (c0 >> 1);
                Ahi[word] = hi; Alo[word] = lo;
            }
            {
                float v0 = (acc[mt][q][2] - mu[mt * 2 + 1]) * rs[mt * 2 + 1] * ga0 + be0;
                float v1 = (acc[mt][q][3] - mu[mt * 2 + 1]) * rs[mt * 2 + 1] * ga1 + be1;
                float w0 = v0 / (1.0f + __expf(-v0));
                float w1 = v1 / (1.0f + __expf(-v1));
                uint32_t lo, hi = pack_split(w0, w1, lo);
                int word = (rlo + 8) * PADW + (c0 >> 1);
                Ahi[word] = hi; Alo[word] = lo;
            }
        }

    // ---- GEMM2: C2(128x128) = A2 @ W4T^T ----
#pragma unroll
    for (int mt = 0; mt < 2; mt++)
#pragma unroll
        for (int nt = 0; nt < 8; nt++)
#pragma unroll
            for (int f = 0; f < 4; f++) acc[mt][nt][f] = 0.f;

    __syncthreads();
    load_b128((uint4*)Bsm, (const uint4*)g_w4h, 0);
    __syncthreads();
    gemm_pass<0>(Ahi, Bsm, acc, mr, nwBase, g, tg);
    gemm_pass<0>(Alo, Bsm, acc, mr, nwBase, g, tg);
    __syncthreads();
    load_b128((uint4*)Bsm, (const uint4*)g_w4l, 0);
    __syncthreads();
    gemm_pass<0>(Ahi, Bsm, acc, mr, nwBase, g, tg);

    // ---- epilogue 2: +b4, store ----
#pragma unroll
    for (int mt = 0; mt < 2; mt++)
#pragma unroll
        for (int nt = 0; nt < 8; nt++) {
            int c0 = nwBase + nt * 8 + 2 * tg;
            float bb0 = sm_b4[c0], bb1 = sm_b4[c0 + 1];
            int rlo = rowBase + mr + mt * 16 + g;
            *(float2*)(out + (size_t)rlo * DD + c0) = make_float2(acc[mt][nt][0] + bb0, acc[mt][nt][1] + bb1);
            *(float2*)(out + (size_t)(rlo + 8) * DD + c0) = make_float2(acc[mt][nt][2] + bb0, acc[mt][nt][3] + bb1);
        }
}

// ---------------- host side: stream/events created once at load ----------------
struct HostCtx {
    cudaStream_t s2;
    cudaEvent_t evStart, evTable, evSide;
    HostCtx() {
        cudaStreamCreateWithFlags(&s2, cudaStreamNonBlocking);
        cudaEventCreateWithFlags(&evStart, cudaEventDisableTiming);
        cudaEventCreateWithFlags(&evTable, cudaEventDisableTiming);
        cudaEventCreateWithFlags(&evSide, cudaEventDisableTiming);
    }
};
static HostCtx g_ctx;

extern "C" void kernel_launch(void* const* d_in, const int* in_sizes, int n_in,
                              void* d_out, int out_size) {
    const float* x = (const float*)d_in[0];
    const float* h = (const float*)d_in[1];
    const void* ei = d_in[2];
    int base = (in_sizes[3] == 1) ? 4 : 3;
    const float* W1 = (const float*)d_in[base + 0];
    const float* b1 = (const float*)d_in[base + 1];
    const float* W2 = (const float*)d_in[base + 2];
    const float* b2 = (const float*)d_in[base + 3];
    const float* W3 = (const float*)d_in[base + 4];
    const float* b3 = (const float*)d_in[base + 5];
    const float* ga = (const float*)d_in[base + 6];
    const float* be = (const float*)d_in[base + 7];
    const float* W4 = (const float*)d_in[base + 8];
    const float* b4 = (const float*)d_in[base + 9];
    float* out = (float*)d_out;

    const int E = in_sizes[2] / 2;

    cudaFuncSetAttribute(node_kernel, cudaFuncAttributeMaxDynamicSharedMemorySize, SMEM_NODE);

    // fork side stream
    cudaEventRecord(g_ctx.evStart, 0);
    cudaStreamWaitEvent(g_ctx.s2, g_ctx.evStart, 0);

    // side stream: table (half-size, ~5 µs) -> evTable -> wsplit -> evSide
    table_kernel<<<TABP / 32, 128, 0, g_ctx.s2>>>(W1, b1, W2, b2);
    cudaEventRecord(g_ctx.evTable, g_ctx.s2);
    wsplit_kernel<<<(256 * 256 + 128 * 256 + 255) / 256, 256, 0, g_ctx.s2>>>(W3, W4);
    cudaEventRecord(g_ctx.evSide, g_ctx.s2);

    // main stream: zero(+detect+h16+x4) -> [table] -> edge (2 edges/warp) -> [wsplit] -> node
    zero_kernel<<<512, 256>>>((const int*)ei, h, x);
    cudaStreamWaitEvent(0, g_ctx.evTable, 0);
    int edge_warps = (E + 1) / 2;
    int edge_blocks = (edge_warps * 32 + 255) / 256;
    edge_kernel<<<edge_blocks, 256>>>(ei, E);
    cudaStreamWaitEvent(0, g_ctx.evSide, 0);
    node_kernel<<<NODES / 128, 256, SMEM_NODE>>>(h, b3, ga, be, b4, out);

    (void)n_in; (void)out_size;
}